// round 5
// baseline (speedup 1.0000x reference)
#include <cuda_runtime.h>
#include <math.h>

// ---------------- problem constants ----------------
#define BB    8
#define NN    8192
#define SS    2048
#define KK    32
#define CPTS  64
#define MM    (BB*SS*KK)            // 524288 rows
#define OUT_XYZ_ELEMS (BB*SS*3)     // 49152 floats of new_xyz at front of output

typedef unsigned long long u64;

// ---------------- device scratch ----------------
__device__ int    g_ballidx[MM];
__device__ float  g_x0[(size_t)MM*64];
__device__ float  g_x1[(size_t)MM*64];
__device__ float2 g_pool2[(size_t)BB*SS*128];
__device__ double g_sum[128];
__device__ double g_sumsq[128];
__device__ float  g_aff_a[128];
__device__ float  g_aff_c[128];

// ---------------- packed f32x2 helpers ----------------
__device__ __forceinline__ u64 pack2(float lo, float hi){
    u64 r; asm("mov.b64 %0, {%1, %2};" : "=l"(r) : "f"(lo), "f"(hi)); return r;
}
__device__ __forceinline__ u64 dup2(float v){
    u64 r; asm("mov.b64 %0, {%1, %1};" : "=l"(r) : "f"(v)); return r;
}
__device__ __forceinline__ void unpack2(u64 v, float& lo, float& hi){
    asm("mov.b64 {%0, %1}, %2;" : "=f"(lo), "=f"(hi) : "l"(v));
}
__device__ __forceinline__ u64 add2(u64 a, u64 b){
    u64 r; asm("add.rn.f32x2 %0, %1, %2;" : "=l"(r) : "l"(a), "l"(b)); return r;
}
__device__ __forceinline__ u64 mul2(u64 a, u64 b){
    u64 r; asm("mul.rn.f32x2 %0, %1, %2;" : "=l"(r) : "l"(a), "l"(b)); return r;
}
__device__ __forceinline__ u64 fma2(u64 a, u64 b, u64 c){
    u64 r; asm("fma.rn.f32x2 %0, %1, %2, %3;" : "=l"(r) : "l"(a), "l"(b), "l"(c)); return r;
}
__device__ __forceinline__ unsigned smem_addr32(const void* p){
    return (unsigned)__cvta_generic_to_shared(p);
}
__device__ __forceinline__ void st_cluster_u64(unsigned addr, u64 v){
    asm volatile("st.shared::cluster.u64 [%0], %1;" :: "r"(addr), "l"(v) : "memory");
}
__device__ __forceinline__ unsigned mapa_sh(unsigned addr, unsigned rank){
    unsigned r; asm("mapa.shared::cluster.u32 %0, %1, %2;" : "=r"(r) : "r"(addr), "r"(rank)); return r;
}

// =====================================================================
// 1) FPS, cluster version: 8 CTAs per batch (cluster), 512 thr/CTA,
//    2 points/thread packed f32x2. Per iteration:
//      local slice min-dist update + argmax -> intra-CTA reduce ->
//      all-to-all record exchange (st.shared::cluster) -> cluster.sync ->
//      per-thread reduce of 8 records (winner key + coords).
//    Exact semantics: same fma chain, first-global-index tie-break.
// =====================================================================
#define FPS_CTAS 8
#define FPS_THR  512

__global__ void __launch_bounds__(FPS_THR,1) __cluster_dims__(FPS_CTAS,1,1)
k_fps(const float* __restrict__ xyz, float* __restrict__ out)
{
    __shared__ u64 sx[FPS_THR], sy[FPS_THR], sz[FPS_THR];  // slice coords (2 pts/thr)
    __shared__ u64 skey[16];                               // per-warp winners
    __shared__ u64 sK[16], sXY[16], sZ[16];                // records, double buffered

    unsigned rank = blockIdx.x & (FPS_CTAS-1);
    int      b    = blockIdx.x >> 3;
    int base = rank * (NN/FPS_CTAS);          // 1024 points per CTA
    const float* X = xyz + (size_t)b*NN*3;
    int t = threadIdx.x, lane = t & 31, wid = t >> 5;

    // load slice coords: points p0=base+2t, p1=p0+1 packed (lo,hi)
    u64 cx, cy, cz;
    {
        int p0 = base + 2*t;
        float x0=X[p0*3+0], y0=X[p0*3+1], z0=X[p0*3+2];
        float x1=X[p0*3+3], y1=X[p0*3+4], z1=X[p0*3+5];
        cx=pack2(x0,x1); cy=pack2(y0,y1); cz=pack2(z0,z1);
        sx[t]=cx; sy[t]=cy; sz[t]=cz;
    }
    float md0=1e10f, md1=1e10f;
    __syncthreads();

    float lx=X[0], ly=X[1], lz=X[2];
    float* onew = out + (size_t)b*SS*3;

    unsigned recK_base  = smem_addr32(sK);
    unsigned recXY_base = smem_addr32(sXY);
    unsigned recZ_base  = smem_addr32(sZ);

    for (int s=0;s<SS;s++){
        if (rank==0 && t==0){ onew[s*3+0]=lx; onew[s*3+1]=ly; onew[s*3+2]=lz; }
        u64 nlx=dup2(-lx), nly=dup2(-ly), nlz=dup2(-lz);

        u64 dx=add2(cx,nlx), dy=add2(cy,nly), dz=add2(cz,nlz);
        u64 dd=fma2(dz,dz,fma2(dy,dy,mul2(dx,dx)));
        float d0,d1; unpack2(dd,d0,d1);
        md0=fminf(md0,d0); md1=fminf(md1,d1);
        float bv=fmaxf(md0,md1);
        int   gi=base + 2*t + ((md0==bv) ? 0 : 1);   // smallest index on tie

        unsigned bits = __float_as_uint(bv);
        unsigned rmax = __reduce_max_sync(0xffffffffu, bits);
        unsigned cand = (bits==rmax) ? (unsigned)gi : 0xffffffffu;
        unsigned gmin = __reduce_min_sync(0xffffffffu, cand);
        if (lane==0) skey[wid] = ((u64)rmax<<32) | (u64)(0xffffffffu - gmin);
        __syncthreads();

        int parity = s & 1, slot = parity*8 + (int)rank;
        if (wid==0){
            u64 k2 = skey[lane & 15];
#pragma unroll
            for (int off=8; off>0; off>>=1){
                unsigned klo = (unsigned)k2, khi = (unsigned)(k2>>32);
                unsigned olo = __shfl_xor_sync(0xffffffffu, klo, off);
                unsigned ohi = __shfl_xor_sync(0xffffffffu, khi, off);
                u64 o = ((u64)ohi<<32) | olo;
                if (o > k2) k2 = o;
            }
            // decode CTA winner, fetch its coords from our slice
            int giw = (int)(0xffffffffu - (unsigned)k2);
            int li  = giw - base, sl = li >> 1, h = li & 1;
            float ax,axh, ay,ayh, az,azh;
            unpack2(sx[sl],ax,axh); unpack2(sy[sl],ay,ayh); unpack2(sz[sl],az,azh);
            float wx = h?axh:ax, wy = h?ayh:ay, wz = h?azh:az;
            u64 vxy = pack2(wx,wy), vz = pack2(wz,wz);
            if (lane < FPS_CTAS){
                unsigned off8 = (unsigned)slot*8u;
                st_cluster_u64(mapa_sh(recK_base  + off8, lane), k2);
                st_cluster_u64(mapa_sh(recXY_base + off8, lane), vxy);
                st_cluster_u64(mapa_sh(recZ_base  + off8, lane), vz);
            }
        }
        asm volatile("barrier.cluster.arrive.aligned;" ::: "memory");
        asm volatile("barrier.cluster.wait.aligned;" ::: "memory");

        // every thread reduces the 8 records (broadcast LDS, conflict-free)
        int pb = parity*8;
        u64 bk = sK[pb]; int bi = pb;
#pragma unroll
        for (int j=1;j<8;j++){
            u64 kj = sK[pb+j];
            if (kj > bk){ bk=kj; bi=pb+j; }
        }
        float hy; unpack2(sXY[bi], lx, ly);
        unpack2(sZ[bi], lz, hy);
    }
}

// =====================================================================
// 2) Ball query (unchanged)
// =====================================================================
__global__ void __launch_bounds__(256,1) k_ballq(const float* __restrict__ xyz,
                                                 const float* __restrict__ newxyz)
{
    extern __shared__ __align__(16) unsigned char s_raw[];
    float4* sp = (float4*)s_raw;

    int b     = blockIdx.x >> 5;
    int sbase = (blockIdx.x & 31) * 64;
    const float* X = xyz + (size_t)b*NN*3;

    for (int j=threadIdx.x; j<NN; j+=256){
        float x=X[j*3+0], y=X[j*3+1], z=X[j*3+2];
        float pp=__fmaf_rn(z,z,__fmaf_rn(y,y,__fmul_rn(x,x)));
        sp[j]=make_float4(x,y,z,pp);
    }
    __syncthreads();

    int wid=threadIdx.x>>5, lane=threadIdx.x&31;
    for (int ci=0; ci<8; ci++){
        int s = sbase + wid*8 + ci;
        const float* q = newxyz + ((size_t)b*SS + s)*3;
        float qx=q[0], qy=q[1], qz=q[2];
        float qq=__fmaf_rn(qz,qz,__fmaf_rn(qy,qy,__fmul_rn(qx,qx)));
        int* o = g_ballidx + ((size_t)b*SS + s)*KK;
        int cnt=0, first=0; bool havefirst=false;

        for (int base=0; base<NN; base+=32){
            float4 p = sp[base+lane];
            float dot=__fmaf_rn(qz,p.z,__fmaf_rn(qy,p.y,__fmul_rn(qx,p.x)));
            float d2 =__fmaf_rn(-2.0f,dot,__fadd_rn(qq,p.w));
            bool valid = (d2 <= 0.0625f);
            unsigned m = __ballot_sync(0xffffffffu, valid);
            if (m){
                if (!havefirst){ first = base + (__ffs(m)-1); havefirst=true; }
                int pre = __popc(m & ((1u<<lane)-1u));
                if (valid && (cnt+pre) < KK) o[cnt+pre] = base+lane;
                cnt += __popc(m);
                if (cnt >= KK) break;
            }
        }
        if (cnt < KK){
            for (int p=cnt+lane; p<KK; p+=32) o[p]=first;
        }
    }
}

// =====================================================================
// 3) stats helpers
// =====================================================================
__global__ void k_zero(){
    if (threadIdx.x < 128){ g_sum[threadIdx.x]=0.0; g_sumsq[threadIdx.x]=0.0; }
}

__global__ void k_finalize(const float* __restrict__ g, const float* __restrict__ be, int C)
{
    int c = threadIdx.x;
    if (c < C){
        double mean = g_sum[c]   * (1.0/(double)MM);
        double var  = g_sumsq[c] * (1.0/(double)MM) - mean*mean;
        double a = (double)g[c] / sqrt(var + 1e-5);
        g_aff_a[c] = (float)a;
        g_aff_c[c] = (float)((double)be[c] - mean*a);
        g_sum[c]=0.0; g_sumsq[c]=0.0;
    }
}

// =====================================================================
// 4) layer 0: gather + GEMM [128 rows x 64 cols], K=67, f32x2 row-pair packed.
// =====================================================================
__global__ void __launch_bounds__(128) k_layer0(const float* __restrict__ xyz,
                                                const float* __restrict__ pts,
                                                const float* __restrict__ newxyz,
                                                const float* __restrict__ w0,
                                                const float* __restrict__ b0)
{
    extern __shared__ __align__(16) unsigned char s_raw[];
    u64*   sfP = (u64*)s_raw;                       // [67][64] pairs, k-major
    float* sw  = (float*)(s_raw + 67*64*8);         // [67][64] k-major
    int t = threadIdx.x;
    size_t row0 = (size_t)blockIdx.x * 128;

    for (int i=t; i<67*64; i+=128){
        int o = i/67, c = i%67;
        int cp = (c>=3) ? (c-3) : (64+c);
        sw[cp*64+o] = w0[i];
    }
    {
        int p = t & 63, h = t >> 6;
        size_t r0g = row0 + 2*p, r1g = r0g + 1;
        int bs = (int)(r0g >> 5);
        int b  = bs >> 11;
        int n0 = g_ballidx[r0g], n1 = g_ballidx[r1g];
        const float4* ra = (const float4*)(pts + ((size_t)b*NN + n0)*CPTS) + h*8;
        const float4* rb = (const float4*)(pts + ((size_t)b*NN + n1)*CPTS) + h*8;
        int c0 = h*32;
#pragma unroll
        for (int v=0; v<8; v++){
            float4 a = ra[v], b4 = rb[v];
            int c = c0 + v*4;
            sfP[(c+0)*64+p]=pack2(a.x,b4.x);
            sfP[(c+1)*64+p]=pack2(a.y,b4.y);
            sfP[(c+2)*64+p]=pack2(a.z,b4.z);
            sfP[(c+3)*64+p]=pack2(a.w,b4.w);
        }
        if (h==0){
            const float* p3a = xyz + ((size_t)b*NN + n0)*3;
            const float* p3b = xyz + ((size_t)b*NN + n1)*3;
            const float* c3  = newxyz + (size_t)bs*3;
            sfP[64*64+p]=pack2(p3a[0]-c3[0], p3b[0]-c3[0]);
            sfP[65*64+p]=pack2(p3a[1]-c3[1], p3b[1]-c3[1]);
            sfP[66*64+p]=pack2(p3a[2]-c3[2], p3b[2]-c3[2]);
        }
    }
    __syncthreads();

    int tx = t & 7, tp = t >> 3;
    u64 acc[4][8];
#pragma unroll
    for (int i=0;i<4;i++)
#pragma unroll
        for (int j=0;j<8;j++) acc[i][j]=0ull;

    for (int k=0;k<64;k+=4){
#pragma unroll
        for (int kk=0;kk<4;kk++){
            const u64* arow = sfP + (size_t)(k+kk)*64 + tp*4;
            ulonglong2 v0 = *(const ulonglong2*)arow;
            ulonglong2 v1 = *(const ulonglong2*)(arow+2);
            const float4* brow = (const float4*)(sw + (size_t)(k+kk)*64 + tx*8);
            float4 b0v=brow[0], b1v=brow[1];
            u64 bb[8];
            bb[0]=dup2(b0v.x); bb[1]=dup2(b0v.y); bb[2]=dup2(b0v.z); bb[3]=dup2(b0v.w);
            bb[4]=dup2(b1v.x); bb[5]=dup2(b1v.y); bb[6]=dup2(b1v.z); bb[7]=dup2(b1v.w);
            u64 a0=v0.x,a1=v0.y,a2=v1.x,a3=v1.y;
#pragma unroll
            for (int j=0;j<8;j++){
                acc[0][j]=fma2(a0,bb[j],acc[0][j]);
                acc[1][j]=fma2(a1,bb[j],acc[1][j]);
                acc[2][j]=fma2(a2,bb[j],acc[2][j]);
                acc[3][j]=fma2(a3,bb[j],acc[3][j]);
            }
        }
    }
#pragma unroll
    for (int k=64;k<67;k++){
        const u64* arow = sfP + (size_t)k*64 + tp*4;
        ulonglong2 v0 = *(const ulonglong2*)arow;
        ulonglong2 v1 = *(const ulonglong2*)(arow+2);
        const float4* brow = (const float4*)(sw + (size_t)k*64 + tx*8);
        float4 b0v=brow[0], b1v=brow[1];
        u64 bb[8];
        bb[0]=dup2(b0v.x); bb[1]=dup2(b0v.y); bb[2]=dup2(b0v.z); bb[3]=dup2(b0v.w);
        bb[4]=dup2(b1v.x); bb[5]=dup2(b1v.y); bb[6]=dup2(b1v.z); bb[7]=dup2(b1v.w);
        u64 a0=v0.x,a1=v0.y,a2=v1.x,a3=v1.y;
#pragma unroll
        for (int j=0;j<8;j++){
            acc[0][j]=fma2(a0,bb[j],acc[0][j]);
            acc[1][j]=fma2(a1,bb[j],acc[1][j]);
            acc[2][j]=fma2(a2,bb[j],acc[2][j]);
            acc[3][j]=fma2(a3,bb[j],acc[3][j]);
        }
    }

    u64 bP[8];
    {
        float4 b0v = *(const float4*)&b0[tx*8];
        float4 b1v = *(const float4*)&b0[tx*8+4];
        bP[0]=dup2(b0v.x); bP[1]=dup2(b0v.y); bP[2]=dup2(b0v.z); bP[3]=dup2(b0v.w);
        bP[4]=dup2(b1v.x); bP[5]=dup2(b1v.y); bP[6]=dup2(b1v.z); bP[7]=dup2(b1v.w);
    }
    float s1[8], s2[8];
#pragma unroll
    for (int j=0;j<8;j++){ s1[j]=0.f; s2[j]=0.f; }
#pragma unroll
    for (int i=0;i<4;i++){
        size_t ra = row0 + (size_t)(tp*4+i)*2;
        float lo[8], hi[8];
#pragma unroll
        for (int j=0;j<8;j++){
            u64 v = add2(acc[i][j], bP[j]);
            unpack2(v, lo[j], hi[j]);
            s1[j]+=lo[j]; s1[j]+=hi[j];
            s2[j]=fmaf(lo[j],lo[j],s2[j]); s2[j]=fmaf(hi[j],hi[j],s2[j]);
        }
        *(float4*)&g_x0[ra*64 + tx*8]       = make_float4(lo[0],lo[1],lo[2],lo[3]);
        *(float4*)&g_x0[ra*64 + tx*8 + 4]   = make_float4(lo[4],lo[5],lo[6],lo[7]);
        *(float4*)&g_x0[(ra+1)*64 + tx*8]   = make_float4(hi[0],hi[1],hi[2],hi[3]);
        *(float4*)&g_x0[(ra+1)*64 + tx*8+4] = make_float4(hi[4],hi[5],hi[6],hi[7]);
    }
    __syncthreads();
    float2* part = (float2*)s_raw;   // [16][64]
#pragma unroll
    for (int j=0;j<8;j++) part[tp*64 + tx*8 + j] = make_float2(s1[j], s2[j]);
    __syncthreads();
    if (t < 64){
        float ss1=0.f, ss2=0.f;
#pragma unroll
        for (int r=0;r<16;r++){ float2 v = part[r*64+t]; ss1+=v.x; ss2+=v.y; }
        atomicAdd(&g_sum[t],   (double)ss1);
        atomicAdd(&g_sumsq[t], (double)ss2);
    }
}

// =====================================================================
// 5) layer 1: relu(affine(x0)) @ W^T + b, 128x64 tile, f32x2 packed
// =====================================================================
__global__ void __launch_bounds__(128) k_layer1(const float* __restrict__ xin,
                                                const float* __restrict__ w,
                                                const float* __restrict__ bias,
                                                float* __restrict__ xout)
{
    extern __shared__ __align__(16) unsigned char s_raw[];
    u64*   sfP = (u64*)s_raw;                       // [64][64]
    float* sw  = (float*)(s_raw + 64*64*8);         // [64][64]
    int t = threadIdx.x;
    size_t row0 = (size_t)blockIdx.x * 128;

    for (int i=t; i<64*64; i+=128){
        int o=i>>6, c=i&63;
        sw[c*64+o] = w[i];
    }
    {
        int p = t & 63, h = t >> 6;
        const float4* ra = (const float4*)(xin + (row0 + 2*p)*64) + h*8;
        const float4* rb = (const float4*)(xin + (row0 + 2*p+1)*64) + h*8;
        int c0 = h*32;
#pragma unroll
        for (int v=0; v<8; v++){
            float4 a = ra[v], b4 = rb[v];
            int c = c0 + v*4;
            float a0=fmaxf(fmaf(a.x, g_aff_a[c+0], g_aff_c[c+0]),0.f);
            float a1=fmaxf(fmaf(a.y, g_aff_a[c+1], g_aff_c[c+1]),0.f);
            float a2=fmaxf(fmaf(a.z, g_aff_a[c+2], g_aff_c[c+2]),0.f);
            float a3=fmaxf(fmaf(a.w, g_aff_a[c+3], g_aff_c[c+3]),0.f);
            float b0=fmaxf(fmaf(b4.x,g_aff_a[c+0], g_aff_c[c+0]),0.f);
            float b1=fmaxf(fmaf(b4.y,g_aff_a[c+1], g_aff_c[c+1]),0.f);
            float b2=fmaxf(fmaf(b4.z,g_aff_a[c+2], g_aff_c[c+2]),0.f);
            float b3=fmaxf(fmaf(b4.w,g_aff_a[c+3], g_aff_c[c+3]),0.f);
            sfP[(c+0)*64+p]=pack2(a0,b0);
            sfP[(c+1)*64+p]=pack2(a1,b1);
            sfP[(c+2)*64+p]=pack2(a2,b2);
            sfP[(c+3)*64+p]=pack2(a3,b3);
        }
    }
    __syncthreads();

    int tx = t & 7, tp = t >> 3;
    u64 acc[4][8];
#pragma unroll
    for (int i=0;i<4;i++)
#pragma unroll
        for (int j=0;j<8;j++) acc[i][j]=0ull;

    for (int k=0;k<64;k+=4){
#pragma unroll
        for (int kk=0;kk<4;kk++){
            const u64* arow = sfP + (size_t)(k+kk)*64 + tp*4;
            ulonglong2 v0 = *(const ulonglong2*)arow;
            ulonglong2 v1 = *(const ulonglong2*)(arow+2);
            const float4* brow = (const float4*)(sw + (size_t)(k+kk)*64 + tx*8);
            float4 b0v=brow[0], b1v=brow[1];
            u64 bb[8];
            bb[0]=dup2(b0v.x); bb[1]=dup2(b0v.y); bb[2]=dup2(b0v.z); bb[3]=dup2(b0v.w);
            bb[4]=dup2(b1v.x); bb[5]=dup2(b1v.y); bb[6]=dup2(b1v.z); bb[7]=dup2(b1v.w);
            u64 a0=v0.x,a1=v0.y,a2=v1.x,a3=v1.y;
#pragma unroll
            for (int j=0;j<8;j++){
                acc[0][j]=fma2(a0,bb[j],acc[0][j]);
                acc[1][j]=fma2(a1,bb[j],acc[1][j]);
                acc[2][j]=fma2(a2,bb[j],acc[2][j]);
                acc[3][j]=fma2(a3,bb[j],acc[3][j]);
            }
        }
    }

    u64 bP[8];
    {
        float4 b0v = *(const float4*)&bias[tx*8];
        float4 b1v = *(const float4*)&bias[tx*8+4];
        bP[0]=dup2(b0v.x); bP[1]=dup2(b0v.y); bP[2]=dup2(b0v.z); bP[3]=dup2(b0v.w);
        bP[4]=dup2(b1v.x); bP[5]=dup2(b1v.y); bP[6]=dup2(b1v.z); bP[7]=dup2(b1v.w);
    }
    float s1[8], s2[8];
#pragma unroll
    for (int j=0;j<8;j++){ s1[j]=0.f; s2[j]=0.f; }
#pragma unroll
    for (int i=0;i<4;i++){
        size_t ra = row0 + (size_t)(tp*4+i)*2;
        float lo[8], hi[8];
#pragma unroll
        for (int j=0;j<8;j++){
            u64 v = add2(acc[i][j], bP[j]);
            unpack2(v, lo[j], hi[j]);
            s1[j]+=lo[j]; s1[j]+=hi[j];
            s2[j]=fmaf(lo[j],lo[j],s2[j]); s2[j]=fmaf(hi[j],hi[j],s2[j]);
        }
        *(float4*)&xout[ra*64 + tx*8]       = make_float4(lo[0],lo[1],lo[2],lo[3]);
        *(float4*)&xout[ra*64 + tx*8 + 4]   = make_float4(lo[4],lo[5],lo[6],lo[7]);
        *(float4*)&xout[(ra+1)*64 + tx*8]   = make_float4(hi[0],hi[1],hi[2],hi[3]);
        *(float4*)&xout[(ra+1)*64 + tx*8+4] = make_float4(hi[4],hi[5],hi[6],hi[7]);
    }
    __syncthreads();
    float2* part = (float2*)s_raw;
#pragma unroll
    for (int j=0;j<8;j++) part[tp*64 + tx*8 + j] = make_float2(s1[j], s2[j]);
    __syncthreads();
    if (t < 64){
        float ss1=0.f, ss2=0.f;
#pragma unroll
        for (int r=0;r<16;r++){ float2 v = part[r*64+t]; ss1+=v.x; ss2+=v.y; }
        atomicAdd(&g_sum[t],   (double)ss1);
        atomicAdd(&g_sumsq[t], (double)ss2);
    }
}

// =====================================================================
// 6) layer 2: relu(affine(x1)) @ W^T + b, 128x128 tile, f32x2 packed.
//    No x2 materialization: fused stats + per-(b,s) raw max/min over K.
// =====================================================================
__global__ void __launch_bounds__(256) k_layer2(const float* __restrict__ xin,
                                                const float* __restrict__ w,
                                                const float* __restrict__ bias)
{
    extern __shared__ __align__(16) unsigned char s_raw[];
    u64*   sfP = (u64*)s_raw;                       // [64][64]  32KB
    float* sw  = (float*)(s_raw + 64*64*8);         // [64][128] 32KB
    int t = threadIdx.x;
    size_t row0 = (size_t)blockIdx.x * 128;

    for (int i=t; i<128*64; i+=256){
        int o=i>>6, c=i&63;
        sw[c*128+o] = w[i];
    }
    {
        int p = t & 63, q = t >> 6;
        const float4* ra = (const float4*)(xin + (row0 + 2*p)*64) + q*4;
        const float4* rb = (const float4*)(xin + (row0 + 2*p+1)*64) + q*4;
        int c0 = q*16;
#pragma unroll
        for (int v=0; v<4; v++){
            float4 a = ra[v], b4 = rb[v];
            int c = c0 + v*4;
            float a0=fmaxf(fmaf(a.x, g_aff_a[c+0], g_aff_c[c+0]),0.f);
            float a1=fmaxf(fmaf(a.y, g_aff_a[c+1], g_aff_c[c+1]),0.f);
            float a2=fmaxf(fmaf(a.z, g_aff_a[c+2], g_aff_c[c+2]),0.f);
            float a3=fmaxf(fmaf(a.w, g_aff_a[c+3], g_aff_c[c+3]),0.f);
            float b0=fmaxf(fmaf(b4.x,g_aff_a[c+0], g_aff_c[c+0]),0.f);
            float b1=fmaxf(fmaf(b4.y,g_aff_a[c+1], g_aff_c[c+1]),0.f);
            float b2=fmaxf(fmaf(b4.z,g_aff_a[c+2], g_aff_c[c+2]),0.f);
            float b3=fmaxf(fmaf(b4.w,g_aff_a[c+3], g_aff_c[c+3]),0.f);
            sfP[(c+0)*64+p]=pack2(a0,b0);
            sfP[(c+1)*64+p]=pack2(a1,b1);
            sfP[(c+2)*64+p]=pack2(a2,b2);
            sfP[(c+3)*64+p]=pack2(a3,b3);
        }
    }
    __syncthreads();

    int tx = t & 15, tp = t >> 4;
    u64 acc[4][8];
#pragma unroll
    for (int i=0;i<4;i++)
#pragma unroll
        for (int j=0;j<8;j++) acc[i][j]=0ull;

    for (int k=0;k<64;k+=4){
#pragma unroll
        for (int kk=0;kk<4;kk++){
            const u64* arow = sfP + (size_t)(k+kk)*64 + tp*4;
            ulonglong2 v0 = *(const ulonglong2*)arow;
            ulonglong2 v1 = *(const ulonglong2*)(arow+2);
            const float4* brow = (const float4*)(sw + (size_t)(k+kk)*128 + tx*8);
            float4 b0v=brow[0], b1v=brow[1];
            u64 bb[8];
            bb[0]=dup2(b0v.x); bb[1]=dup2(b0v.y); bb[2]=dup2(b0v.z); bb[3]=dup2(b0v.w);
            bb[4]=dup2(b1v.x); bb[5]=dup2(b1v.y); bb[6]=dup2(b1v.z); bb[7]=dup2(b1v.w);
            u64 a0=v0.x,a1=v0.y,a2=v1.x,a3=v1.y;
#pragma unroll
            for (int j=0;j<8;j++){
                acc[0][j]=fma2(a0,bb[j],acc[0][j]);
                acc[1][j]=fma2(a1,bb[j],acc[1][j]);
                acc[2][j]=fma2(a2,bb[j],acc[2][j]);
                acc[3][j]=fma2(a3,bb[j],acc[3][j]);
            }
        }
    }

    u64 bP[8];
    {
        float4 b0v = *(const float4*)&bias[tx*8];
        float4 b1v = *(const float4*)&bias[tx*8+4];
        bP[0]=dup2(b0v.x); bP[1]=dup2(b0v.y); bP[2]=dup2(b0v.z); bP[3]=dup2(b0v.w);
        bP[4]=dup2(b1v.x); bP[5]=dup2(b1v.y); bP[6]=dup2(b1v.z); bP[7]=dup2(b1v.w);
    }
    float s1[8], s2[8], mx[8], mn[8];
#pragma unroll
    for (int j=0;j<8;j++){ s1[j]=0.f; s2[j]=0.f; mx[j]=-3.4e38f; mn[j]=3.4e38f; }
#pragma unroll
    for (int i=0;i<4;i++){
#pragma unroll
        for (int j=0;j<8;j++){
            u64 v = add2(acc[i][j], bP[j]);
            float lo, hi; unpack2(v, lo, hi);
            s1[j]+=lo; s1[j]+=hi;
            s2[j]=fmaf(lo,lo,s2[j]); s2[j]=fmaf(hi,hi,s2[j]);
            mx[j]=fmaxf(mx[j], fmaxf(lo,hi));
            mn[j]=fminf(mn[j], fminf(lo,hi));
        }
    }
    __syncthreads();
    float4* part = (float4*)s_raw;   // [16][128] = 32KB
#pragma unroll
    for (int j=0;j<8;j++) part[tp*128 + tx*8 + j] = make_float4(s1[j], s2[j], mx[j], mn[j]);
    __syncthreads();

    for (int u=t; u<512; u+=256){
        int g = u >> 7, c = u & 127;
        float gmx=-3.4e38f, gmn=3.4e38f;
#pragma unroll
        for (int r=0;r<4;r++){
            float4 v = part[(g*4+r)*128 + c];
            gmx=fmaxf(gmx, v.z); gmn=fminf(gmn, v.w);
        }
        g_pool2[((size_t)blockIdx.x*4 + g)*128 + c] = make_float2(gmx, gmn);
    }
    if (t < 128){
        float ss1=0.f, ss2=0.f;
#pragma unroll
        for (int r=0;r<16;r++){ float4 v = part[r*128+t]; ss1+=v.x; ss2+=v.y; }
        atomicAdd(&g_sum[t],   (double)ss1);
        atomicAdd(&g_sumsq[t], (double)ss2);
    }
}

// =====================================================================
// 7) final pool: out = relu(a * rawmax + c)  (a<0 -> rawmin)
// =====================================================================
__global__ void __launch_bounds__(256) k_pool(float* __restrict__ out)
{
    int idx = blockIdx.x*256 + threadIdx.x;
    int c = idx & 127;
    float2 v = g_pool2[idx];
    float a = g_aff_a[c], cc = g_aff_c[c];
    float raw = (a >= 0.f) ? v.x : v.y;
    out[OUT_XYZ_ELEMS + idx] = fmaxf(fmaf(raw, a, cc), 0.f);
}

// =====================================================================
// launch
// =====================================================================
extern "C" void kernel_launch(void* const* d_in, const int* in_sizes, int n_in,
                              void* d_out, int out_size)
{
    const float* xyz = (const float*)d_in[0];
    const float* pts = (const float*)d_in[1];
    const float* w0  = (const float*)d_in[2];
    const float* b0  = (const float*)d_in[3];
    const float* g0  = (const float*)d_in[4];
    const float* be0 = (const float*)d_in[5];
    const float* w1  = (const float*)d_in[6];
    const float* b1  = (const float*)d_in[7];
    const float* g1  = (const float*)d_in[8];
    const float* be1 = (const float*)d_in[9];
    const float* w2  = (const float*)d_in[10];
    const float* b2  = (const float*)d_in[11];
    const float* g2  = (const float*)d_in[12];
    const float* be2 = (const float*)d_in[13];
    float* out = (float*)d_out;

    float *px0, *px1;
    cudaGetSymbolAddress((void**)&px0, g_x0);
    cudaGetSymbolAddress((void**)&px1, g_x1);

    cudaFuncSetAttribute(k_ballq,  cudaFuncAttributeMaxDynamicSharedMemorySize, 131072);
    cudaFuncSetAttribute(k_layer0, cudaFuncAttributeMaxDynamicSharedMemorySize, 51456);
    cudaFuncSetAttribute(k_layer1, cudaFuncAttributeMaxDynamicSharedMemorySize, 49152);
    cudaFuncSetAttribute(k_layer2, cudaFuncAttributeMaxDynamicSharedMemorySize, 65536);

    k_fps  <<<BB*FPS_CTAS, FPS_THR>>>(xyz, out);
    k_ballq<<<BB*(SS/64), 256, 131072>>>(xyz, out);
    k_zero <<<1,128>>>();
    k_layer0<<<MM/128, 128, 51456>>>(xyz, pts, out, w0, b0);
    k_finalize<<<1,128>>>(g0, be0, 64);
    k_layer1<<<MM/128, 128, 49152>>>(px0, w1, b1, px1);
    k_finalize<<<1,128>>>(g1, be1, 64);
    k_layer2<<<MM/128, 256, 65536>>>(px1, w2, b2);
    k_finalize<<<1,128>>>(g2, be2, 128);
    k_pool <<<(BB*SS*128)/256, 256>>>(out);
}

// round 6
// speedup vs baseline: 1.0642x; 1.0642x over previous
#include <cuda_runtime.h>
#include <math.h>

// ---------------- problem constants ----------------
#define BB    8
#define NN    8192
#define SS    2048
#define KK    32
#define CPTS  64
#define MM    (BB*SS*KK)            // 524288 rows
#define OUT_XYZ_ELEMS (BB*SS*3)     // 49152 floats of new_xyz at front of output

typedef unsigned long long u64;

// ---------------- device scratch ----------------
__device__ int    g_ballidx[MM];
__device__ float  g_x0[(size_t)MM*64];
__device__ float  g_x1[(size_t)MM*64];
__device__ float2 g_pool2[(size_t)BB*SS*128];
__device__ double g_sum[128];
__device__ double g_sumsq[128];
__device__ float  g_aff_a[128];
__device__ float  g_aff_c[128];

// ---------------- packed f32x2 helpers ----------------
__device__ __forceinline__ u64 pack2(float lo, float hi){
    u64 r; asm("mov.b64 %0, {%1, %2};" : "=l"(r) : "f"(lo), "f"(hi)); return r;
}
__device__ __forceinline__ u64 dup2(float v){
    u64 r; asm("mov.b64 %0, {%1, %1};" : "=l"(r) : "f"(v)); return r;
}
__device__ __forceinline__ void unpack2(u64 v, float& lo, float& hi){
    asm("mov.b64 {%0, %1}, %2;" : "=f"(lo), "=f"(hi) : "l"(v));
}
__device__ __forceinline__ u64 add2(u64 a, u64 b){
    u64 r; asm("add.rn.f32x2 %0, %1, %2;" : "=l"(r) : "l"(a), "l"(b)); return r;
}
__device__ __forceinline__ u64 mul2(u64 a, u64 b){
    u64 r; asm("mul.rn.f32x2 %0, %1, %2;" : "=l"(r) : "l"(a), "l"(b)); return r;
}
__device__ __forceinline__ u64 fma2(u64 a, u64 b, u64 c){
    u64 r; asm("fma.rn.f32x2 %0, %1, %2, %3;" : "=l"(r) : "l"(a), "l"(b), "l"(c)); return r;
}

// =====================================================================
// 1) FPS: 1 block/batch, 1024 threads, 8 pts/thread in registers (f32x2).
//    ONE barrier per iteration: per-warp REDUX winner -> skey[wid] ->
//    __syncthreads -> every warp redundantly reduces all 32 keys via
//    shfl_xor and looks up winner coords (broadcast LDS). skey is
//    parity-double-buffered to avoid WAR across the single barrier.
// =====================================================================
__global__ void __launch_bounds__(1024,1) k_fps(const float* __restrict__ xyz,
                                                float* __restrict__ out)
{
    extern __shared__ __align__(16) unsigned char smraw[];
    u64* sx2  = (u64*)smraw;       // 4096
    u64* sy2  = sx2 + 4096;
    u64* sz2  = sy2 + 4096;
    u64* skey = sz2 + 4096;        // 64 (2 x 32, parity buffered)

    int b = blockIdx.x;
    const float* X = xyz + (size_t)b*NN*3;
    int t = threadIdx.x, lane = t & 31, wid = t >> 5;

    u64 cx[4], cy[4], cz[4];
    float md[8];
#pragma unroll
    for (int p=0;p<4;p++){
        int j0 = (2*p)*1024 + t, j1 = j0 + 1024;
        float x0=X[j0*3+0], y0=X[j0*3+1], z0=X[j0*3+2];
        float x1=X[j1*3+0], y1=X[j1*3+1], z1=X[j1*3+2];
        cx[p]=pack2(x0,x1); cy[p]=pack2(y0,y1); cz[p]=pack2(z0,z1);
        sx2[p*1024+t]=cx[p]; sy2[p*1024+t]=cy[p]; sz2[p*1024+t]=cz[p];
        md[2*p]=1e10f; md[2*p+1]=1e10f;
    }
    __syncthreads();

    float lx=X[0], ly=X[1], lz=X[2];
    float* onew = out + (size_t)b*SS*3;

    for (int s=0;s<SS;s++){
        if (t==0){ onew[s*3+0]=lx; onew[s*3+1]=ly; onew[s*3+2]=lz; }
        u64 nlx=dup2(-lx), nly=dup2(-ly), nlz=dup2(-lz);

        float bv=-1.0f;
#pragma unroll
        for (int p=0;p<4;p++){
            u64 dx=add2(cx[p],nlx);
            u64 dy=add2(cy[p],nly);
            u64 dz=add2(cz[p],nlz);
            u64 dd=fma2(dz,dz,fma2(dy,dy,mul2(dx,dx)));
            float d0,d1; unpack2(dd,d0,d1);
            float m0=fminf(md[2*p],d0);   md[2*p]=m0;
            float m1=fminf(md[2*p+1],d1); md[2*p+1]=m1;
            bv=fmaxf(bv,m0); bv=fmaxf(bv,m1);
        }
        // first index whose md equals bv (smallest i wins)
        int bj = 7*1024 + t;
#pragma unroll
        for (int i=6;i>=0;i--) bj = (md[i]==bv) ? (i*1024+t) : bj;

        unsigned bits = __float_as_uint(bv);
        unsigned rmax = __reduce_max_sync(0xffffffffu, bits);
        unsigned cand = (bits==rmax) ? (unsigned)bj : 0xffffffffu;
        unsigned jw   = __reduce_min_sync(0xffffffffu, cand);

        int pb = (s & 1) * 32;
        if (lane==0) skey[pb + wid] = ((u64)rmax<<32) | (u64)(0xffffffffu - jw);
        __syncthreads();

        // every warp reduces all 32 keys
        u64 k2 = skey[pb + lane];
#pragma unroll
        for (int off=16; off>0; off>>=1){
            u64 o = __shfl_xor_sync(0xffffffffu, k2, off);
            if (o > k2) k2 = o;
        }
        int j = (int)(0xffffffffu - (unsigned)k2);
        int p = j >> 11, h = (j >> 10) & 1, tt = j & 1023;
        float a0,a1;
        unpack2(sx2[p*1024+tt],a0,a1); lx = h ? a1 : a0;
        unpack2(sy2[p*1024+tt],a0,a1); ly = h ? a1 : a0;
        unpack2(sz2[p*1024+tt],a0,a1); lz = h ? a1 : a0;
    }
}

// =====================================================================
// 2) Ball query (unchanged)
// =====================================================================
__global__ void __launch_bounds__(256,1) k_ballq(const float* __restrict__ xyz,
                                                 const float* __restrict__ newxyz)
{
    extern __shared__ __align__(16) unsigned char s_raw[];
    float4* sp = (float4*)s_raw;

    int b     = blockIdx.x >> 5;
    int sbase = (blockIdx.x & 31) * 64;
    const float* X = xyz + (size_t)b*NN*3;

    for (int j=threadIdx.x; j<NN; j+=256){
        float x=X[j*3+0], y=X[j*3+1], z=X[j*3+2];
        float pp=__fmaf_rn(z,z,__fmaf_rn(y,y,__fmul_rn(x,x)));
        sp[j]=make_float4(x,y,z,pp);
    }
    __syncthreads();

    int wid=threadIdx.x>>5, lane=threadIdx.x&31;
    for (int ci=0; ci<8; ci++){
        int s = sbase + wid*8 + ci;
        const float* q = newxyz + ((size_t)b*SS + s)*3;
        float qx=q[0], qy=q[1], qz=q[2];
        float qq=__fmaf_rn(qz,qz,__fmaf_rn(qy,qy,__fmul_rn(qx,qx)));
        int* o = g_ballidx + ((size_t)b*SS + s)*KK;
        int cnt=0, first=0; bool havefirst=false;

        for (int base=0; base<NN; base+=32){
            float4 p = sp[base+lane];
            float dot=__fmaf_rn(qz,p.z,__fmaf_rn(qy,p.y,__fmul_rn(qx,p.x)));
            float d2 =__fmaf_rn(-2.0f,dot,__fadd_rn(qq,p.w));
            bool valid = (d2 <= 0.0625f);
            unsigned m = __ballot_sync(0xffffffffu, valid);
            if (m){
                if (!havefirst){ first = base + (__ffs(m)-1); havefirst=true; }
                int pre = __popc(m & ((1u<<lane)-1u));
                if (valid && (cnt+pre) < KK) o[cnt+pre] = base+lane;
                cnt += __popc(m);
                if (cnt >= KK) break;
            }
        }
        if (cnt < KK){
            for (int p=cnt+lane; p<KK; p+=32) o[p]=first;
        }
    }
}

// =====================================================================
// 3) stats helpers
// =====================================================================
__global__ void k_zero(){
    if (threadIdx.x < 128){ g_sum[threadIdx.x]=0.0; g_sumsq[threadIdx.x]=0.0; }
}

__global__ void k_finalize(const float* __restrict__ g, const float* __restrict__ be, int C)
{
    int c = threadIdx.x;
    if (c < C){
        double mean = g_sum[c]   * (1.0/(double)MM);
        double var  = g_sumsq[c] * (1.0/(double)MM) - mean*mean;
        double a = (double)g[c] / sqrt(var + 1e-5);
        g_aff_a[c] = (float)a;
        g_aff_c[c] = (float)((double)be[c] - mean*a);
        g_sum[c]=0.0; g_sumsq[c]=0.0;
    }
}

// =====================================================================
// 4) layer 0: gather + GEMM [128 rows x 64 cols], K=67, f32x2 row-pair packed.
// =====================================================================
__global__ void __launch_bounds__(128) k_layer0(const float* __restrict__ xyz,
                                                const float* __restrict__ pts,
                                                const float* __restrict__ newxyz,
                                                const float* __restrict__ w0,
                                                const float* __restrict__ b0)
{
    extern __shared__ __align__(16) unsigned char s_raw[];
    u64*   sfP = (u64*)s_raw;                       // [67][64] pairs, k-major
    float* sw  = (float*)(s_raw + 67*64*8);         // [67][64] k-major
    int t = threadIdx.x;
    size_t row0 = (size_t)blockIdx.x * 128;

    for (int i=t; i<67*64; i+=128){
        int o = i/67, c = i%67;
        int cp = (c>=3) ? (c-3) : (64+c);
        sw[cp*64+o] = w0[i];
    }
    {
        int p = t & 63, h = t >> 6;
        size_t r0g = row0 + 2*p, r1g = r0g + 1;
        int bs = (int)(r0g >> 5);
        int b  = bs >> 11;
        int n0 = g_ballidx[r0g], n1 = g_ballidx[r1g];
        const float4* ra = (const float4*)(pts + ((size_t)b*NN + n0)*CPTS) + h*8;
        const float4* rb = (const float4*)(pts + ((size_t)b*NN + n1)*CPTS) + h*8;
        int c0 = h*32;
#pragma unroll
        for (int v=0; v<8; v++){
            float4 a = ra[v], b4 = rb[v];
            int c = c0 + v*4;
            sfP[(c+0)*64+p]=pack2(a.x,b4.x);
            sfP[(c+1)*64+p]=pack2(a.y,b4.y);
            sfP[(c+2)*64+p]=pack2(a.z,b4.z);
            sfP[(c+3)*64+p]=pack2(a.w,b4.w);
        }
        if (h==0){
            const float* p3a = xyz + ((size_t)b*NN + n0)*3;
            const float* p3b = xyz + ((size_t)b*NN + n1)*3;
            const float* c3  = newxyz + (size_t)bs*3;
            sfP[64*64+p]=pack2(p3a[0]-c3[0], p3b[0]-c3[0]);
            sfP[65*64+p]=pack2(p3a[1]-c3[1], p3b[1]-c3[1]);
            sfP[66*64+p]=pack2(p3a[2]-c3[2], p3b[2]-c3[2]);
        }
    }
    __syncthreads();

    int tx = t & 7, tp = t >> 3;
    u64 acc[4][8];
#pragma unroll
    for (int i=0;i<4;i++)
#pragma unroll
        for (int j=0;j<8;j++) acc[i][j]=0ull;

    for (int k=0;k<64;k+=4){
#pragma unroll
        for (int kk=0;kk<4;kk++){
            const u64* arow = sfP + (size_t)(k+kk)*64 + tp*4;
            ulonglong2 v0 = *(const ulonglong2*)arow;
            ulonglong2 v1 = *(const ulonglong2*)(arow+2);
            const float4* brow = (const float4*)(sw + (size_t)(k+kk)*64 + tx*8);
            float4 b0v=brow[0], b1v=brow[1];
            u64 bb[8];
            bb[0]=dup2(b0v.x); bb[1]=dup2(b0v.y); bb[2]=dup2(b0v.z); bb[3]=dup2(b0v.w);
            bb[4]=dup2(b1v.x); bb[5]=dup2(b1v.y); bb[6]=dup2(b1v.z); bb[7]=dup2(b1v.w);
            u64 a0=v0.x,a1=v0.y,a2=v1.x,a3=v1.y;
#pragma unroll
            for (int j=0;j<8;j++){
                acc[0][j]=fma2(a0,bb[j],acc[0][j]);
                acc[1][j]=fma2(a1,bb[j],acc[1][j]);
                acc[2][j]=fma2(a2,bb[j],acc[2][j]);
                acc[3][j]=fma2(a3,bb[j],acc[3][j]);
            }
        }
    }
#pragma unroll
    for (int k=64;k<67;k++){
        const u64* arow = sfP + (size_t)k*64 + tp*4;
        ulonglong2 v0 = *(const ulonglong2*)arow;
        ulonglong2 v1 = *(const ulonglong2*)(arow+2);
        const float4* brow = (const float4*)(sw + (size_t)k*64 + tx*8);
        float4 b0v=brow[0], b1v=brow[1];
        u64 bb[8];
        bb[0]=dup2(b0v.x); bb[1]=dup2(b0v.y); bb[2]=dup2(b0v.z); bb[3]=dup2(b0v.w);
        bb[4]=dup2(b1v.x); bb[5]=dup2(b1v.y); bb[6]=dup2(b1v.z); bb[7]=dup2(b1v.w);
        u64 a0=v0.x,a1=v0.y,a2=v1.x,a3=v1.y;
#pragma unroll
        for (int j=0;j<8;j++){
            acc[0][j]=fma2(a0,bb[j],acc[0][j]);
            acc[1][j]=fma2(a1,bb[j],acc[1][j]);
            acc[2][j]=fma2(a2,bb[j],acc[2][j]);
            acc[3][j]=fma2(a3,bb[j],acc[3][j]);
        }
    }

    u64 bP[8];
    {
        float4 b0v = *(const float4*)&b0[tx*8];
        float4 b1v = *(const float4*)&b0[tx*8+4];
        bP[0]=dup2(b0v.x); bP[1]=dup2(b0v.y); bP[2]=dup2(b0v.z); bP[3]=dup2(b0v.w);
        bP[4]=dup2(b1v.x); bP[5]=dup2(b1v.y); bP[6]=dup2(b1v.z); bP[7]=dup2(b1v.w);
    }
    float s1[8], s2[8];
#pragma unroll
    for (int j=0;j<8;j++){ s1[j]=0.f; s2[j]=0.f; }
#pragma unroll
    for (int i=0;i<4;i++){
        size_t ra = row0 + (size_t)(tp*4+i)*2;
        float lo[8], hi[8];
#pragma unroll
        for (int j=0;j<8;j++){
            u64 v = add2(acc[i][j], bP[j]);
            unpack2(v, lo[j], hi[j]);
            s1[j]+=lo[j]; s1[j]+=hi[j];
            s2[j]=fmaf(lo[j],lo[j],s2[j]); s2[j]=fmaf(hi[j],hi[j],s2[j]);
        }
        *(float4*)&g_x0[ra*64 + tx*8]       = make_float4(lo[0],lo[1],lo[2],lo[3]);
        *(float4*)&g_x0[ra*64 + tx*8 + 4]   = make_float4(lo[4],lo[5],lo[6],lo[7]);
        *(float4*)&g_x0[(ra+1)*64 + tx*8]   = make_float4(hi[0],hi[1],hi[2],hi[3]);
        *(float4*)&g_x0[(ra+1)*64 + tx*8+4] = make_float4(hi[4],hi[5],hi[6],hi[7]);
    }
    __syncthreads();
    float2* part = (float2*)s_raw;   // [16][64]
#pragma unroll
    for (int j=0;j<8;j++) part[tp*64 + tx*8 + j] = make_float2(s1[j], s2[j]);
    __syncthreads();
    if (t < 64){
        float ss1=0.f, ss2=0.f;
#pragma unroll
        for (int r=0;r<16;r++){ float2 v = part[r*64+t]; ss1+=v.x; ss2+=v.y; }
        atomicAdd(&g_sum[t],   (double)ss1);
        atomicAdd(&g_sumsq[t], (double)ss2);
    }
}

// =====================================================================
// 5) layer 1: relu(affine(x0)) @ W^T + b, 128x64 tile, f32x2 packed
// =====================================================================
__global__ void __launch_bounds__(128) k_layer1(const float* __restrict__ xin,
                                                const float* __restrict__ w,
                                                const float* __restrict__ bias,
                                                float* __restrict__ xout)
{
    extern __shared__ __align__(16) unsigned char s_raw[];
    u64*   sfP = (u64*)s_raw;                       // [64][64]
    float* sw  = (float*)(s_raw + 64*64*8);         // [64][64]
    int t = threadIdx.x;
    size_t row0 = (size_t)blockIdx.x * 128;

    for (int i=t; i<64*64; i+=128){
        int o=i>>6, c=i&63;
        sw[c*64+o] = w[i];
    }
    {
        int p = t & 63, h = t >> 6;
        const float4* ra = (const float4*)(xin + (row0 + 2*p)*64) + h*8;
        const float4* rb = (const float4*)(xin + (row0 + 2*p+1)*64) + h*8;
        int c0 = h*32;
#pragma unroll
        for (int v=0; v<8; v++){
            float4 a = ra[v], b4 = rb[v];
            int c = c0 + v*4;
            float a0=fmaxf(fmaf(a.x, g_aff_a[c+0], g_aff_c[c+0]),0.f);
            float a1=fmaxf(fmaf(a.y, g_aff_a[c+1], g_aff_c[c+1]),0.f);
            float a2=fmaxf(fmaf(a.z, g_aff_a[c+2], g_aff_c[c+2]),0.f);
            float a3=fmaxf(fmaf(a.w, g_aff_a[c+3], g_aff_c[c+3]),0.f);
            float b0=fmaxf(fmaf(b4.x,g_aff_a[c+0], g_aff_c[c+0]),0.f);
            float b1=fmaxf(fmaf(b4.y,g_aff_a[c+1], g_aff_c[c+1]),0.f);
            float b2=fmaxf(fmaf(b4.z,g_aff_a[c+2], g_aff_c[c+2]),0.f);
            float b3=fmaxf(fmaf(b4.w,g_aff_a[c+3], g_aff_c[c+3]),0.f);
            sfP[(c+0)*64+p]=pack2(a0,b0);
            sfP[(c+1)*64+p]=pack2(a1,b1);
            sfP[(c+2)*64+p]=pack2(a2,b2);
            sfP[(c+3)*64+p]=pack2(a3,b3);
        }
    }
    __syncthreads();

    int tx = t & 7, tp = t >> 3;
    u64 acc[4][8];
#pragma unroll
    for (int i=0;i<4;i++)
#pragma unroll
        for (int j=0;j<8;j++) acc[i][j]=0ull;

    for (int k=0;k<64;k+=4){
#pragma unroll
        for (int kk=0;kk<4;kk++){
            const u64* arow = sfP + (size_t)(k+kk)*64 + tp*4;
            ulonglong2 v0 = *(const ulonglong2*)arow;
            ulonglong2 v1 = *(const ulonglong2*)(arow+2);
            const float4* brow = (const float4*)(sw + (size_t)(k+kk)*64 + tx*8);
            float4 b0v=brow[0], b1v=brow[1];
            u64 bb[8];
            bb[0]=dup2(b0v.x); bb[1]=dup2(b0v.y); bb[2]=dup2(b0v.z); bb[3]=dup2(b0v.w);
            bb[4]=dup2(b1v.x); bb[5]=dup2(b1v.y); bb[6]=dup2(b1v.z); bb[7]=dup2(b1v.w);
            u64 a0=v0.x,a1=v0.y,a2=v1.x,a3=v1.y;
#pragma unroll
            for (int j=0;j<8;j++){
                acc[0][j]=fma2(a0,bb[j],acc[0][j]);
                acc[1][j]=fma2(a1,bb[j],acc[1][j]);
                acc[2][j]=fma2(a2,bb[j],acc[2][j]);
                acc[3][j]=fma2(a3,bb[j],acc[3][j]);
            }
        }
    }

    u64 bP[8];
    {
        float4 b0v = *(const float4*)&bias[tx*8];
        float4 b1v = *(const float4*)&bias[tx*8+4];
        bP[0]=dup2(b0v.x); bP[1]=dup2(b0v.y); bP[2]=dup2(b0v.z); bP[3]=dup2(b0v.w);
        bP[4]=dup2(b1v.x); bP[5]=dup2(b1v.y); bP[6]=dup2(b1v.z); bP[7]=dup2(b1v.w);
    }
    float s1[8], s2[8];
#pragma unroll
    for (int j=0;j<8;j++){ s1[j]=0.f; s2[j]=0.f; }
#pragma unroll
    for (int i=0;i<4;i++){
        size_t ra = row0 + (size_t)(tp*4+i)*2;
        float lo[8], hi[8];
#pragma unroll
        for (int j=0;j<8;j++){
            u64 v = add2(acc[i][j], bP[j]);
            unpack2(v, lo[j], hi[j]);
            s1[j]+=lo[j]; s1[j]+=hi[j];
            s2[j]=fmaf(lo[j],lo[j],s2[j]); s2[j]=fmaf(hi[j],hi[j],s2[j]);
        }
        *(float4*)&xout[ra*64 + tx*8]       = make_float4(lo[0],lo[1],lo[2],lo[3]);
        *(float4*)&xout[ra*64 + tx*8 + 4]   = make_float4(lo[4],lo[5],lo[6],lo[7]);
        *(float4*)&xout[(ra+1)*64 + tx*8]   = make_float4(hi[0],hi[1],hi[2],hi[3]);
        *(float4*)&xout[(ra+1)*64 + tx*8+4] = make_float4(hi[4],hi[5],hi[6],hi[7]);
    }
    __syncthreads();
    float2* part = (float2*)s_raw;
#pragma unroll
    for (int j=0;j<8;j++) part[tp*64 + tx*8 + j] = make_float2(s1[j], s2[j]);
    __syncthreads();
    if (t < 64){
        float ss1=0.f, ss2=0.f;
#pragma unroll
        for (int r=0;r<16;r++){ float2 v = part[r*64+t]; ss1+=v.x; ss2+=v.y; }
        atomicAdd(&g_sum[t],   (double)ss1);
        atomicAdd(&g_sumsq[t], (double)ss2);
    }
}

// =====================================================================
// 6) layer 2: relu(affine(x1)) @ W^T + b, 128x128 tile, f32x2 packed.
//    No x2 materialization: fused stats + per-(b,s) raw max/min over K.
// =====================================================================
__global__ void __launch_bounds__(256) k_layer2(const float* __restrict__ xin,
                                                const float* __restrict__ w,
                                                const float* __restrict__ bias)
{
    extern __shared__ __align__(16) unsigned char s_raw[];
    u64*   sfP = (u64*)s_raw;                       // [64][64]  32KB
    float* sw  = (float*)(s_raw + 64*64*8);         // [64][128] 32KB
    int t = threadIdx.x;
    size_t row0 = (size_t)blockIdx.x * 128;

    for (int i=t; i<128*64; i+=256){
        int o=i>>6, c=i&63;
        sw[c*128+o] = w[i];
    }
    {
        int p = t & 63, q = t >> 6;
        const float4* ra = (const float4*)(xin + (row0 + 2*p)*64) + q*4;
        const float4* rb = (const float4*)(xin + (row0 + 2*p+1)*64) + q*4;
        int c0 = q*16;
#pragma unroll
        for (int v=0; v<4; v++){
            float4 a = ra[v], b4 = rb[v];
            int c = c0 + v*4;
            float a0=fmaxf(fmaf(a.x, g_aff_a[c+0], g_aff_c[c+0]),0.f);
            float a1=fmaxf(fmaf(a.y, g_aff_a[c+1], g_aff_c[c+1]),0.f);
            float a2=fmaxf(fmaf(a.z, g_aff_a[c+2], g_aff_c[c+2]),0.f);
            float a3=fmaxf(fmaf(a.w, g_aff_a[c+3], g_aff_c[c+3]),0.f);
            float b0=fmaxf(fmaf(b4.x,g_aff_a[c+0], g_aff_c[c+0]),0.f);
            float b1=fmaxf(fmaf(b4.y,g_aff_a[c+1], g_aff_c[c+1]),0.f);
            float b2=fmaxf(fmaf(b4.z,g_aff_a[c+2], g_aff_c[c+2]),0.f);
            float b3=fmaxf(fmaf(b4.w,g_aff_a[c+3], g_aff_c[c+3]),0.f);
            sfP[(c+0)*64+p]=pack2(a0,b0);
            sfP[(c+1)*64+p]=pack2(a1,b1);
            sfP[(c+2)*64+p]=pack2(a2,b2);
            sfP[(c+3)*64+p]=pack2(a3,b3);
        }
    }
    __syncthreads();

    int tx = t & 15, tp = t >> 4;
    u64 acc[4][8];
#pragma unroll
    for (int i=0;i<4;i++)
#pragma unroll
        for (int j=0;j<8;j++) acc[i][j]=0ull;

    for (int k=0;k<64;k+=4){
#pragma unroll
        for (int kk=0;kk<4;kk++){
            const u64* arow = sfP + (size_t)(k+kk)*64 + tp*4;
            ulonglong2 v0 = *(const ulonglong2*)arow;
            ulonglong2 v1 = *(const ulonglong2*)(arow+2);
            const float4* brow = (const float4*)(sw + (size_t)(k+kk)*128 + tx*8);
            float4 b0v=brow[0], b1v=brow[1];
            u64 bb[8];
            bb[0]=dup2(b0v.x); bb[1]=dup2(b0v.y); bb[2]=dup2(b0v.z); bb[3]=dup2(b0v.w);
            bb[4]=dup2(b1v.x); bb[5]=dup2(b1v.y); bb[6]=dup2(b1v.z); bb[7]=dup2(b1v.w);
            u64 a0=v0.x,a1=v0.y,a2=v1.x,a3=v1.y;
#pragma unroll
            for (int j=0;j<8;j++){
                acc[0][j]=fma2(a0,bb[j],acc[0][j]);
                acc[1][j]=fma2(a1,bb[j],acc[1][j]);
                acc[2][j]=fma2(a2,bb[j],acc[2][j]);
                acc[3][j]=fma2(a3,bb[j],acc[3][j]);
            }
        }
    }

    u64 bP[8];
    {
        float4 b0v = *(const float4*)&bias[tx*8];
        float4 b1v = *(const float4*)&bias[tx*8+4];
        bP[0]=dup2(b0v.x); bP[1]=dup2(b0v.y); bP[2]=dup2(b0v.z); bP[3]=dup2(b0v.w);
        bP[4]=dup2(b1v.x); bP[5]=dup2(b1v.y); bP[6]=dup2(b1v.z); bP[7]=dup2(b1v.w);
    }
    float s1[8], s2[8], mx[8], mn[8];
#pragma unroll
    for (int j=0;j<8;j++){ s1[j]=0.f; s2[j]=0.f; mx[j]=-3.4e38f; mn[j]=3.4e38f; }
#pragma unroll
    for (int i=0;i<4;i++){
#pragma unroll
        for (int j=0;j<8;j++){
            u64 v = add2(acc[i][j], bP[j]);
            float lo, hi; unpack2(v, lo, hi);
            s1[j]+=lo; s1[j]+=hi;
            s2[j]=fmaf(lo,lo,s2[j]); s2[j]=fmaf(hi,hi,s2[j]);
            mx[j]=fmaxf(mx[j], fmaxf(lo,hi));
            mn[j]=fminf(mn[j], fminf(lo,hi));
        }
    }
    __syncthreads();
    float4* part = (float4*)s_raw;   // [16][128] = 32KB
#pragma unroll
    for (int j=0;j<8;j++) part[tp*128 + tx*8 + j] = make_float4(s1[j], s2[j], mx[j], mn[j]);
    __syncthreads();

    for (int u=t; u<512; u+=256){
        int g = u >> 7, c = u & 127;
        float gmx=-3.4e38f, gmn=3.4e38f;
#pragma unroll
        for (int r=0;r<4;r++){
            float4 v = part[(g*4+r)*128 + c];
            gmx=fmaxf(gmx, v.z); gmn=fminf(gmn, v.w);
        }
        g_pool2[((size_t)blockIdx.x*4 + g)*128 + c] = make_float2(gmx, gmn);
    }
    if (t < 128){
        float ss1=0.f, ss2=0.f;
#pragma unroll
        for (int r=0;r<16;r++){ float4 v = part[r*128+t]; ss1+=v.x; ss2+=v.y; }
        atomicAdd(&g_sum[t],   (double)ss1);
        atomicAdd(&g_sumsq[t], (double)ss2);
    }
}

// =====================================================================
// 7) final pool: out = relu(a * rawmax + c)  (a<0 -> rawmin)
// =====================================================================
__global__ void __launch_bounds__(256) k_pool(float* __restrict__ out)
{
    int idx = blockIdx.x*256 + threadIdx.x;
    int c = idx & 127;
    float2 v = g_pool2[idx];
    float a = g_aff_a[c], cc = g_aff_c[c];
    float raw = (a >= 0.f) ? v.x : v.y;
    out[OUT_XYZ_ELEMS + idx] = fmaxf(fmaf(raw, a, cc), 0.f);
}

// =====================================================================
// launch
// =====================================================================
extern "C" void kernel_launch(void* const* d_in, const int* in_sizes, int n_in,
                              void* d_out, int out_size)
{
    const float* xyz = (const float*)d_in[0];
    const float* pts = (const float*)d_in[1];
    const float* w0  = (const float*)d_in[2];
    const float* b0  = (const float*)d_in[3];
    const float* g0  = (const float*)d_in[4];
    const float* be0 = (const float*)d_in[5];
    const float* w1  = (const float*)d_in[6];
    const float* b1  = (const float*)d_in[7];
    const float* g1  = (const float*)d_in[8];
    const float* be1 = (const float*)d_in[9];
    const float* w2  = (const float*)d_in[10];
    const float* b2  = (const float*)d_in[11];
    const float* g2  = (const float*)d_in[12];
    const float* be2 = (const float*)d_in[13];
    float* out = (float*)d_out;

    float *px0, *px1;
    cudaGetSymbolAddress((void**)&px0, g_x0);
    cudaGetSymbolAddress((void**)&px1, g_x1);

    cudaFuncSetAttribute(k_fps,    cudaFuncAttributeMaxDynamicSharedMemorySize, 98816);
    cudaFuncSetAttribute(k_ballq,  cudaFuncAttributeMaxDynamicSharedMemorySize, 131072);
    cudaFuncSetAttribute(k_layer0, cudaFuncAttributeMaxDynamicSharedMemorySize, 51456);
    cudaFuncSetAttribute(k_layer1, cudaFuncAttributeMaxDynamicSharedMemorySize, 49152);
    cudaFuncSetAttribute(k_layer2, cudaFuncAttributeMaxDynamicSharedMemorySize, 65536);

    k_fps  <<<BB, 1024, 98816>>>(xyz, out);
    k_ballq<<<BB*(SS/64), 256, 131072>>>(xyz, out);
    k_zero <<<1,128>>>();
    k_layer0<<<MM/128, 128, 51456>>>(xyz, pts, out, w0, b0);
    k_finalize<<<1,128>>>(g0, be0, 64);
    k_layer1<<<MM/128, 128, 49152>>>(px0, w1, b1, px1);
    k_finalize<<<1,128>>>(g1, be1, 64);
    k_layer2<<<MM/128, 256, 65536>>>(px1, w2, b2);
    k_finalize<<<1,128>>>(g2, be2, 128);
    k_pool <<<(BB*SS*128)/256, 256>>>(out);
}

// round 7
// speedup vs baseline: 1.2827x; 1.2053x over previous
#include <cuda_runtime.h>
#include <math.h>

// ---------------- problem constants ----------------
#define BB    8
#define NN    8192
#define SS    2048
#define KK    32
#define CPTS  64
#define MM    (BB*SS*KK)            // 524288 rows
#define OUT_XYZ_ELEMS (BB*SS*3)     // 49152 floats of new_xyz at front of output

typedef unsigned long long u64;

// ---------------- device scratch ----------------
__device__ int    g_ballidx[MM];
__device__ float  g_x0[(size_t)MM*64];
__device__ float  g_x1[(size_t)MM*64];
__device__ float2 g_pool2[(size_t)BB*SS*128];
__device__ double g_sum[128];
__device__ double g_sumsq[128];
__device__ float  g_aff_a[128];
__device__ float  g_aff_c[128];

// ---------------- packed f32x2 helpers ----------------
__device__ __forceinline__ u64 pack2(float lo, float hi){
    u64 r; asm("mov.b64 %0, {%1, %2};" : "=l"(r) : "f"(lo), "f"(hi)); return r;
}
__device__ __forceinline__ u64 dup2(float v){
    u64 r; asm("mov.b64 %0, {%1, %1};" : "=l"(r) : "f"(v)); return r;
}
__device__ __forceinline__ void unpack2(u64 v, float& lo, float& hi){
    asm("mov.b64 {%0, %1}, %2;" : "=f"(lo), "=f"(hi) : "l"(v));
}
__device__ __forceinline__ u64 add2(u64 a, u64 b){
    u64 r; asm("add.rn.f32x2 %0, %1, %2;" : "=l"(r) : "l"(a), "l"(b)); return r;
}
__device__ __forceinline__ u64 mul2(u64 a, u64 b){
    u64 r; asm("mul.rn.f32x2 %0, %1, %2;" : "=l"(r) : "l"(a), "l"(b)); return r;
}
__device__ __forceinline__ u64 fma2(u64 a, u64 b, u64 c){
    u64 r; asm("fma.rn.f32x2 %0, %1, %2, %3;" : "=l"(r) : "l"(a), "l"(b), "l"(c)); return r;
}

// =====================================================================
// 1) FPS: 1 block/batch, 1024 threads, 8 pts/thread in registers (f32x2).
//    ONE barrier per iteration. Per-warp winner via REDUX; winners stored
//    as SPLIT u32 arrays (dist bits, index). After the barrier EVERY warp
//    reduces the 32 winners with two REDUX ops (max dist, then min index
//    among maxes) -- no u64 shfl chains. Parity double-buffered.
//    Tie-break = min global index among max distance = first-occurrence
//    argmax (distances >= 0 so float-bit compare is exact).
// =====================================================================
__global__ void __launch_bounds__(1024,1) k_fps(const float* __restrict__ xyz,
                                                float* __restrict__ out)
{
    extern __shared__ __align__(16) unsigned char smraw[];
    u64* sx2  = (u64*)smraw;       // 4096
    u64* sy2  = sx2 + 4096;
    u64* sz2  = sy2 + 4096;
    unsigned* sdist = (unsigned*)(sz2 + 4096);   // 64 (2 x 32 parity)
    unsigned* sidx  = sdist + 64;                // 64

    int b = blockIdx.x;
    const float* X = xyz + (size_t)b*NN*3;
    int t = threadIdx.x, lane = t & 31, wid = t >> 5;

    u64 cx[4], cy[4], cz[4];
    float md[8];
#pragma unroll
    for (int p=0;p<4;p++){
        int j0 = (2*p)*1024 + t, j1 = j0 + 1024;
        float x0=X[j0*3+0], y0=X[j0*3+1], z0=X[j0*3+2];
        float x1=X[j1*3+0], y1=X[j1*3+1], z1=X[j1*3+2];
        cx[p]=pack2(x0,x1); cy[p]=pack2(y0,y1); cz[p]=pack2(z0,z1);
        sx2[p*1024+t]=cx[p]; sy2[p*1024+t]=cy[p]; sz2[p*1024+t]=cz[p];
        md[2*p]=1e10f; md[2*p+1]=1e10f;
    }
    __syncthreads();

    float lx=X[0], ly=X[1], lz=X[2];
    float* onew = out + (size_t)b*SS*3;

    for (int s=0;s<SS;s++){
        if (t==0){ onew[s*3+0]=lx; onew[s*3+1]=ly; onew[s*3+2]=lz; }
        u64 nlx=dup2(-lx), nly=dup2(-ly), nlz=dup2(-lz);

        float bv=-1.0f;
#pragma unroll
        for (int p=0;p<4;p++){
            u64 dx=add2(cx[p],nlx);
            u64 dy=add2(cy[p],nly);
            u64 dz=add2(cz[p],nlz);
            u64 dd=fma2(dz,dz,fma2(dy,dy,mul2(dx,dx)));
            float d0,d1; unpack2(dd,d0,d1);
            float m0=fminf(md[2*p],d0);   md[2*p]=m0;
            float m1=fminf(md[2*p+1],d1); md[2*p+1]=m1;
            bv=fmaxf(bv,m0); bv=fmaxf(bv,m1);
        }
        // first index whose md equals bv (smallest i wins)
        int bj = 7*1024 + t;
#pragma unroll
        for (int i=6;i>=0;i--) bj = (md[i]==bv) ? (i*1024+t) : bj;

        unsigned bits = __float_as_uint(bv);
        unsigned rmax = __reduce_max_sync(0xffffffffu, bits);
        unsigned cand = (bits==rmax) ? (unsigned)bj : 0xffffffffu;
        unsigned jw   = __reduce_min_sync(0xffffffffu, cand);

        int pb = (s & 1) * 32;
        if (lane==0){ sdist[pb + wid] = rmax; sidx[pb + wid] = jw; }
        __syncthreads();

        // every warp reduces the 32 winners: 2 LDS.32 + 2 REDUX
        unsigned d2 = sdist[pb + lane];
        unsigned i2 = sidx [pb + lane];
        unsigned gmax = __reduce_max_sync(0xffffffffu, d2);
        unsigned c2   = (d2==gmax) ? i2 : 0xffffffffu;
        unsigned j    = __reduce_min_sync(0xffffffffu, c2);

        int p = (int)(j >> 11), h = (int)((j >> 10) & 1), tt = (int)(j & 1023);
        float a0,a1;
        unpack2(sx2[p*1024+tt],a0,a1); lx = h ? a1 : a0;
        unpack2(sy2[p*1024+tt],a0,a1); ly = h ? a1 : a0;
        unpack2(sz2[p*1024+tt],a0,a1); lz = h ? a1 : a0;
    }
}

// =====================================================================
// 2) Ball query (unchanged)
// =====================================================================
__global__ void __launch_bounds__(256,1) k_ballq(const float* __restrict__ xyz,
                                                 const float* __restrict__ newxyz)
{
    extern __shared__ __align__(16) unsigned char s_raw[];
    float4* sp = (float4*)s_raw;

    int b     = blockIdx.x >> 5;
    int sbase = (blockIdx.x & 31) * 64;
    const float* X = xyz + (size_t)b*NN*3;

    for (int j=threadIdx.x; j<NN; j+=256){
        float x=X[j*3+0], y=X[j*3+1], z=X[j*3+2];
        float pp=__fmaf_rn(z,z,__fmaf_rn(y,y,__fmul_rn(x,x)));
        sp[j]=make_float4(x,y,z,pp);
    }
    __syncthreads();

    int wid=threadIdx.x>>5, lane=threadIdx.x&31;
    for (int ci=0; ci<8; ci++){
        int s = sbase + wid*8 + ci;
        const float* q = newxyz + ((size_t)b*SS + s)*3;
        float qx=q[0], qy=q[1], qz=q[2];
        float qq=__fmaf_rn(qz,qz,__fmaf_rn(qy,qy,__fmul_rn(qx,qx)));
        int* o = g_ballidx + ((size_t)b*SS + s)*KK;
        int cnt=0, first=0; bool havefirst=false;

        for (int base=0; base<NN; base+=32){
            float4 p = sp[base+lane];
            float dot=__fmaf_rn(qz,p.z,__fmaf_rn(qy,p.y,__fmul_rn(qx,p.x)));
            float d2 =__fmaf_rn(-2.0f,dot,__fadd_rn(qq,p.w));
            bool valid = (d2 <= 0.0625f);
            unsigned m = __ballot_sync(0xffffffffu, valid);
            if (m){
                if (!havefirst){ first = base + (__ffs(m)-1); havefirst=true; }
                int pre = __popc(m & ((1u<<lane)-1u));
                if (valid && (cnt+pre) < KK) o[cnt+pre] = base+lane;
                cnt += __popc(m);
                if (cnt >= KK) break;
            }
        }
        if (cnt < KK){
            for (int p=cnt+lane; p<KK; p+=32) o[p]=first;
        }
    }
}

// =====================================================================
// 3) stats helpers
// =====================================================================
__global__ void k_zero(){
    if (threadIdx.x < 128){ g_sum[threadIdx.x]=0.0; g_sumsq[threadIdx.x]=0.0; }
}

__global__ void k_finalize(const float* __restrict__ g, const float* __restrict__ be, int C)
{
    int c = threadIdx.x;
    if (c < C){
        double mean = g_sum[c]   * (1.0/(double)MM);
        double var  = g_sumsq[c] * (1.0/(double)MM) - mean*mean;
        double a = (double)g[c] / sqrt(var + 1e-5);
        g_aff_a[c] = (float)a;
        g_aff_c[c] = (float)((double)be[c] - mean*a);
        g_sum[c]=0.0; g_sumsq[c]=0.0;
    }
}

// =====================================================================
// 4) layer 0: gather + GEMM [128 rows x 64 cols], K=67, f32x2 row-pair packed.
// =====================================================================
__global__ void __launch_bounds__(128) k_layer0(const float* __restrict__ xyz,
                                                const float* __restrict__ pts,
                                                const float* __restrict__ newxyz,
                                                const float* __restrict__ w0,
                                                const float* __restrict__ b0)
{
    extern __shared__ __align__(16) unsigned char s_raw[];
    u64*   sfP = (u64*)s_raw;                       // [67][64] pairs, k-major
    float* sw  = (float*)(s_raw + 67*64*8);         // [67][64] k-major
    int t = threadIdx.x;
    size_t row0 = (size_t)blockIdx.x * 128;

    for (int i=t; i<67*64; i+=128){
        int o = i/67, c = i%67;
        int cp = (c>=3) ? (c-3) : (64+c);
        sw[cp*64+o] = w0[i];
    }
    {
        int p = t & 63, h = t >> 6;
        size_t r0g = row0 + 2*p, r1g = r0g + 1;
        int bs = (int)(r0g >> 5);
        int b  = bs >> 11;
        int n0 = g_ballidx[r0g], n1 = g_ballidx[r1g];
        const float4* ra = (const float4*)(pts + ((size_t)b*NN + n0)*CPTS) + h*8;
        const float4* rb = (const float4*)(pts + ((size_t)b*NN + n1)*CPTS) + h*8;
        int c0 = h*32;
#pragma unroll
        for (int v=0; v<8; v++){
            float4 a = ra[v], b4 = rb[v];
            int c = c0 + v*4;
            sfP[(c+0)*64+p]=pack2(a.x,b4.x);
            sfP[(c+1)*64+p]=pack2(a.y,b4.y);
            sfP[(c+2)*64+p]=pack2(a.z,b4.z);
            sfP[(c+3)*64+p]=pack2(a.w,b4.w);
        }
        if (h==0){
            const float* p3a = xyz + ((size_t)b*NN + n0)*3;
            const float* p3b = xyz + ((size_t)b*NN + n1)*3;
            const float* c3  = newxyz + (size_t)bs*3;
            sfP[64*64+p]=pack2(p3a[0]-c3[0], p3b[0]-c3[0]);
            sfP[65*64+p]=pack2(p3a[1]-c3[1], p3b[1]-c3[1]);
            sfP[66*64+p]=pack2(p3a[2]-c3[2], p3b[2]-c3[2]);
        }
    }
    __syncthreads();

    int tx = t & 7, tp = t >> 3;
    u64 acc[4][8];
#pragma unroll
    for (int i=0;i<4;i++)
#pragma unroll
        for (int j=0;j<8;j++) acc[i][j]=0ull;

    for (int k=0;k<64;k+=4){
#pragma unroll
        for (int kk=0;kk<4;kk++){
            const u64* arow = sfP + (size_t)(k+kk)*64 + tp*4;
            ulonglong2 v0 = *(const ulonglong2*)arow;
            ulonglong2 v1 = *(const ulonglong2*)(arow+2);
            const float4* brow = (const float4*)(sw + (size_t)(k+kk)*64 + tx*8);
            float4 b0v=brow[0], b1v=brow[1];
            u64 bb[8];
            bb[0]=dup2(b0v.x); bb[1]=dup2(b0v.y); bb[2]=dup2(b0v.z); bb[3]=dup2(b0v.w);
            bb[4]=dup2(b1v.x); bb[5]=dup2(b1v.y); bb[6]=dup2(b1v.z); bb[7]=dup2(b1v.w);
            u64 a0=v0.x,a1=v0.y,a2=v1.x,a3=v1.y;
#pragma unroll
            for (int j=0;j<8;j++){
                acc[0][j]=fma2(a0,bb[j],acc[0][j]);
                acc[1][j]=fma2(a1,bb[j],acc[1][j]);
                acc[2][j]=fma2(a2,bb[j],acc[2][j]);
                acc[3][j]=fma2(a3,bb[j],acc[3][j]);
            }
        }
    }
#pragma unroll
    for (int k=64;k<67;k++){
        const u64* arow = sfP + (size_t)k*64 + tp*4;
        ulonglong2 v0 = *(const ulonglong2*)arow;
        ulonglong2 v1 = *(const ulonglong2*)(arow+2);
        const float4* brow = (const float4*)(sw + (size_t)k*64 + tx*8);
        float4 b0v=brow[0], b1v=brow[1];
        u64 bb[8];
        bb[0]=dup2(b0v.x); bb[1]=dup2(b0v.y); bb[2]=dup2(b0v.z); bb[3]=dup2(b0v.w);
        bb[4]=dup2(b1v.x); bb[5]=dup2(b1v.y); bb[6]=dup2(b1v.z); bb[7]=dup2(b1v.w);
        u64 a0=v0.x,a1=v0.y,a2=v1.x,a3=v1.y;
#pragma unroll
        for (int j=0;j<8;j++){
            acc[0][j]=fma2(a0,bb[j],acc[0][j]);
            acc[1][j]=fma2(a1,bb[j],acc[1][j]);
            acc[2][j]=fma2(a2,bb[j],acc[2][j]);
            acc[3][j]=fma2(a3,bb[j],acc[3][j]);
        }
    }

    u64 bP[8];
    {
        float4 b0v = *(const float4*)&b0[tx*8];
        float4 b1v = *(const float4*)&b0[tx*8+4];
        bP[0]=dup2(b0v.x); bP[1]=dup2(b0v.y); bP[2]=dup2(b0v.z); bP[3]=dup2(b0v.w);
        bP[4]=dup2(b1v.x); bP[5]=dup2(b1v.y); bP[6]=dup2(b1v.z); bP[7]=dup2(b1v.w);
    }
    float s1[8], s2[8];
#pragma unroll
    for (int j=0;j<8;j++){ s1[j]=0.f; s2[j]=0.f; }
#pragma unroll
    for (int i=0;i<4;i++){
        size_t ra = row0 + (size_t)(tp*4+i)*2;
        float lo[8], hi[8];
#pragma unroll
        for (int j=0;j<8;j++){
            u64 v = add2(acc[i][j], bP[j]);
            unpack2(v, lo[j], hi[j]);
            s1[j]+=lo[j]; s1[j]+=hi[j];
            s2[j]=fmaf(lo[j],lo[j],s2[j]); s2[j]=fmaf(hi[j],hi[j],s2[j]);
        }
        *(float4*)&g_x0[ra*64 + tx*8]       = make_float4(lo[0],lo[1],lo[2],lo[3]);
        *(float4*)&g_x0[ra*64 + tx*8 + 4]   = make_float4(lo[4],lo[5],lo[6],lo[7]);
        *(float4*)&g_x0[(ra+1)*64 + tx*8]   = make_float4(hi[0],hi[1],hi[2],hi[3]);
        *(float4*)&g_x0[(ra+1)*64 + tx*8+4] = make_float4(hi[4],hi[5],hi[6],hi[7]);
    }
    __syncthreads();
    float2* part = (float2*)s_raw;   // [16][64]
#pragma unroll
    for (int j=0;j<8;j++) part[tp*64 + tx*8 + j] = make_float2(s1[j], s2[j]);
    __syncthreads();
    if (t < 64){
        float ss1=0.f, ss2=0.f;
#pragma unroll
        for (int r=0;r<16;r++){ float2 v = part[r*64+t]; ss1+=v.x; ss2+=v.y; }
        atomicAdd(&g_sum[t],   (double)ss1);
        atomicAdd(&g_sumsq[t], (double)ss2);
    }
}

// =====================================================================
// 5) layer 1: relu(affine(x0)) @ W^T + b, 128x64 tile, f32x2 packed
// =====================================================================
__global__ void __launch_bounds__(128) k_layer1(const float* __restrict__ xin,
                                                const float* __restrict__ w,
                                                const float* __restrict__ bias,
                                                float* __restrict__ xout)
{
    extern __shared__ __align__(16) unsigned char s_raw[];
    u64*   sfP = (u64*)s_raw;                       // [64][64]
    float* sw  = (float*)(s_raw + 64*64*8);         // [64][64]
    int t = threadIdx.x;
    size_t row0 = (size_t)blockIdx.x * 128;

    for (int i=t; i<64*64; i+=128){
        int o=i>>6, c=i&63;
        sw[c*64+o] = w[i];
    }
    {
        int p = t & 63, h = t >> 6;
        const float4* ra = (const float4*)(xin + (row0 + 2*p)*64) + h*8;
        const float4* rb = (const float4*)(xin + (row0 + 2*p+1)*64) + h*8;
        int c0 = h*32;
#pragma unroll
        for (int v=0; v<8; v++){
            float4 a = ra[v], b4 = rb[v];
            int c = c0 + v*4;
            float a0=fmaxf(fmaf(a.x, g_aff_a[c+0], g_aff_c[c+0]),0.f);
            float a1=fmaxf(fmaf(a.y, g_aff_a[c+1], g_aff_c[c+1]),0.f);
            float a2=fmaxf(fmaf(a.z, g_aff_a[c+2], g_aff_c[c+2]),0.f);
            float a3=fmaxf(fmaf(a.w, g_aff_a[c+3], g_aff_c[c+3]),0.f);
            float b0=fmaxf(fmaf(b4.x,g_aff_a[c+0], g_aff_c[c+0]),0.f);
            float b1=fmaxf(fmaf(b4.y,g_aff_a[c+1], g_aff_c[c+1]),0.f);
            float b2=fmaxf(fmaf(b4.z,g_aff_a[c+2], g_aff_c[c+2]),0.f);
            float b3=fmaxf(fmaf(b4.w,g_aff_a[c+3], g_aff_c[c+3]),0.f);
            sfP[(c+0)*64+p]=pack2(a0,b0);
            sfP[(c+1)*64+p]=pack2(a1,b1);
            sfP[(c+2)*64+p]=pack2(a2,b2);
            sfP[(c+3)*64+p]=pack2(a3,b3);
        }
    }
    __syncthreads();

    int tx = t & 7, tp = t >> 3;
    u64 acc[4][8];
#pragma unroll
    for (int i=0;i<4;i++)
#pragma unroll
        for (int j=0;j<8;j++) acc[i][j]=0ull;

    for (int k=0;k<64;k+=4){
#pragma unroll
        for (int kk=0;kk<4;kk++){
            const u64* arow = sfP + (size_t)(k+kk)*64 + tp*4;
            ulonglong2 v0 = *(const ulonglong2*)arow;
            ulonglong2 v1 = *(const ulonglong2*)(arow+2);
            const float4* brow = (const float4*)(sw + (size_t)(k+kk)*64 + tx*8);
            float4 b0v=brow[0], b1v=brow[1];
            u64 bb[8];
            bb[0]=dup2(b0v.x); bb[1]=dup2(b0v.y); bb[2]=dup2(b0v.z); bb[3]=dup2(b0v.w);
            bb[4]=dup2(b1v.x); bb[5]=dup2(b1v.y); bb[6]=dup2(b1v.z); bb[7]=dup2(b1v.w);
            u64 a0=v0.x,a1=v0.y,a2=v1.x,a3=v1.y;
#pragma unroll
            for (int j=0;j<8;j++){
                acc[0][j]=fma2(a0,bb[j],acc[0][j]);
                acc[1][j]=fma2(a1,bb[j],acc[1][j]);
                acc[2][j]=fma2(a2,bb[j],acc[2][j]);
                acc[3][j]=fma2(a3,bb[j],acc[3][j]);
            }
        }
    }

    u64 bP[8];
    {
        float4 b0v = *(const float4*)&bias[tx*8];
        float4 b1v = *(const float4*)&bias[tx*8+4];
        bP[0]=dup2(b0v.x); bP[1]=dup2(b0v.y); bP[2]=dup2(b0v.z); bP[3]=dup2(b0v.w);
        bP[4]=dup2(b1v.x); bP[5]=dup2(b1v.y); bP[6]=dup2(b1v.z); bP[7]=dup2(b1v.w);
    }
    float s1[8], s2[8];
#pragma unroll
    for (int j=0;j<8;j++){ s1[j]=0.f; s2[j]=0.f; }
#pragma unroll
    for (int i=0;i<4;i++){
        size_t ra = row0 + (size_t)(tp*4+i)*2;
        float lo[8], hi[8];
#pragma unroll
        for (int j=0;j<8;j++){
            u64 v = add2(acc[i][j], bP[j]);
            unpack2(v, lo[j], hi[j]);
            s1[j]+=lo[j]; s1[j]+=hi[j];
            s2[j]=fmaf(lo[j],lo[j],s2[j]); s2[j]=fmaf(hi[j],hi[j],s2[j]);
        }
        *(float4*)&xout[ra*64 + tx*8]       = make_float4(lo[0],lo[1],lo[2],lo[3]);
        *(float4*)&xout[ra*64 + tx*8 + 4]   = make_float4(lo[4],lo[5],lo[6],lo[7]);
        *(float4*)&xout[(ra+1)*64 + tx*8]   = make_float4(hi[0],hi[1],hi[2],hi[3]);
        *(float4*)&xout[(ra+1)*64 + tx*8+4] = make_float4(hi[4],hi[5],hi[6],hi[7]);
    }
    __syncthreads();
    float2* part = (float2*)s_raw;
#pragma unroll
    for (int j=0;j<8;j++) part[tp*64 + tx*8 + j] = make_float2(s1[j], s2[j]);
    __syncthreads();
    if (t < 64){
        float ss1=0.f, ss2=0.f;
#pragma unroll
        for (int r=0;r<16;r++){ float2 v = part[r*64+t]; ss1+=v.x; ss2+=v.y; }
        atomicAdd(&g_sum[t],   (double)ss1);
        atomicAdd(&g_sumsq[t], (double)ss2);
    }
}

// =====================================================================
// 6) layer 2: relu(affine(x1)) @ W^T + b, 128x128 tile, f32x2 packed.
//    No x2 materialization: fused stats + per-(b,s) raw max/min over K.
// =====================================================================
__global__ void __launch_bounds__(256) k_layer2(const float* __restrict__ xin,
                                                const float* __restrict__ w,
                                                const float* __restrict__ bias)
{
    extern __shared__ __align__(16) unsigned char s_raw[];
    u64*   sfP = (u64*)s_raw;                       // [64][64]  32KB
    float* sw  = (float*)(s_raw + 64*64*8);         // [64][128] 32KB
    int t = threadIdx.x;
    size_t row0 = (size_t)blockIdx.x * 128;

    for (int i=t; i<128*64; i+=256){
        int o=i>>6, c=i&63;
        sw[c*128+o] = w[i];
    }
    {
        int p = t & 63, q = t >> 6;
        const float4* ra = (const float4*)(xin + (row0 + 2*p)*64) + q*4;
        const float4* rb = (const float4*)(xin + (row0 + 2*p+1)*64) + q*4;
        int c0 = q*16;
#pragma unroll
        for (int v=0; v<4; v++){
            float4 a = ra[v], b4 = rb[v];
            int c = c0 + v*4;
            float a0=fmaxf(fmaf(a.x, g_aff_a[c+0], g_aff_c[c+0]),0.f);
            float a1=fmaxf(fmaf(a.y, g_aff_a[c+1], g_aff_c[c+1]),0.f);
            float a2=fmaxf(fmaf(a.z, g_aff_a[c+2], g_aff_c[c+2]),0.f);
            float a3=fmaxf(fmaf(a.w, g_aff_a[c+3], g_aff_c[c+3]),0.f);
            float b0=fmaxf(fmaf(b4.x,g_aff_a[c+0], g_aff_c[c+0]),0.f);
            float b1=fmaxf(fmaf(b4.y,g_aff_a[c+1], g_aff_c[c+1]),0.f);
            float b2=fmaxf(fmaf(b4.z,g_aff_a[c+2], g_aff_c[c+2]),0.f);
            float b3=fmaxf(fmaf(b4.w,g_aff_a[c+3], g_aff_c[c+3]),0.f);
            sfP[(c+0)*64+p]=pack2(a0,b0);
            sfP[(c+1)*64+p]=pack2(a1,b1);
            sfP[(c+2)*64+p]=pack2(a2,b2);
            sfP[(c+3)*64+p]=pack2(a3,b3);
        }
    }
    __syncthreads();

    int tx = t & 15, tp = t >> 4;
    u64 acc[4][8];
#pragma unroll
    for (int i=0;i<4;i++)
#pragma unroll
        for (int j=0;j<8;j++) acc[i][j]=0ull;

    for (int k=0;k<64;k+=4){
#pragma unroll
        for (int kk=0;kk<4;kk++){
            const u64* arow = sfP + (size_t)(k+kk)*64 + tp*4;
            ulonglong2 v0 = *(const ulonglong2*)arow;
            ulonglong2 v1 = *(const ulonglong2*)(arow+2);
            const float4* brow = (const float4*)(sw + (size_t)(k+kk)*128 + tx*8);
            float4 b0v=brow[0], b1v=brow[1];
            u64 bb[8];
            bb[0]=dup2(b0v.x); bb[1]=dup2(b0v.y); bb[2]=dup2(b0v.z); bb[3]=dup2(b0v.w);
            bb[4]=dup2(b1v.x); bb[5]=dup2(b1v.y); bb[6]=dup2(b1v.z); bb[7]=dup2(b1v.w);
            u64 a0=v0.x,a1=v0.y,a2=v1.x,a3=v1.y;
#pragma unroll
            for (int j=0;j<8;j++){
                acc[0][j]=fma2(a0,bb[j],acc[0][j]);
                acc[1][j]=fma2(a1,bb[j],acc[1][j]);
                acc[2][j]=fma2(a2,bb[j],acc[2][j]);
                acc[3][j]=fma2(a3,bb[j],acc[3][j]);
            }
        }
    }

    u64 bP[8];
    {
        float4 b0v = *(const float4*)&bias[tx*8];
        float4 b1v = *(const float4*)&bias[tx*8+4];
        bP[0]=dup2(b0v.x); bP[1]=dup2(b0v.y); bP[2]=dup2(b0v.z); bP[3]=dup2(b0v.w);
        bP[4]=dup2(b1v.x); bP[5]=dup2(b1v.y); bP[6]=dup2(b1v.z); bP[7]=dup2(b1v.w);
    }
    float s1[8], s2[8], mx[8], mn[8];
#pragma unroll
    for (int j=0;j<8;j++){ s1[j]=0.f; s2[j]=0.f; mx[j]=-3.4e38f; mn[j]=3.4e38f; }
#pragma unroll
    for (int i=0;i<4;i++){
#pragma unroll
        for (int j=0;j<8;j++){
            u64 v = add2(acc[i][j], bP[j]);
            float lo, hi; unpack2(v, lo, hi);
            s1[j]+=lo; s1[j]+=hi;
            s2[j]=fmaf(lo,lo,s2[j]); s2[j]=fmaf(hi,hi,s2[j]);
            mx[j]=fmaxf(mx[j], fmaxf(lo,hi));
            mn[j]=fminf(mn[j], fminf(lo,hi));
        }
    }
    __syncthreads();
    float4* part = (float4*)s_raw;   // [16][128] = 32KB
#pragma unroll
    for (int j=0;j<8;j++) part[tp*128 + tx*8 + j] = make_float4(s1[j], s2[j], mx[j], mn[j]);
    __syncthreads();

    for (int u=t; u<512; u+=256){
        int g = u >> 7, c = u & 127;
        float gmx=-3.4e38f, gmn=3.4e38f;
#pragma unroll
        for (int r=0;r<4;r++){
            float4 v = part[(g*4+r)*128 + c];
            gmx=fmaxf(gmx, v.z); gmn=fminf(gmn, v.w);
        }
        g_pool2[((size_t)blockIdx.x*4 + g)*128 + c] = make_float2(gmx, gmn);
    }
    if (t < 128){
        float ss1=0.f, ss2=0.f;
#pragma unroll
        for (int r=0;r<16;r++){ float4 v = part[r*128+t]; ss1+=v.x; ss2+=v.y; }
        atomicAdd(&g_sum[t],   (double)ss1);
        atomicAdd(&g_sumsq[t], (double)ss2);
    }
}

// =====================================================================
// 7) final pool: out = relu(a * rawmax + c)  (a<0 -> rawmin)
// =====================================================================
__global__ void __launch_bounds__(256) k_pool(float* __restrict__ out)
{
    int idx = blockIdx.x*256 + threadIdx.x;
    int c = idx & 127;
    float2 v = g_pool2[idx];
    float a = g_aff_a[c], cc = g_aff_c[c];
    float raw = (a >= 0.f) ? v.x : v.y;
    out[OUT_XYZ_ELEMS + idx] = fmaxf(fmaf(raw, a, cc), 0.f);
}

// =====================================================================
// launch
// =====================================================================
extern "C" void kernel_launch(void* const* d_in, const int* in_sizes, int n_in,
                              void* d_out, int out_size)
{
    const float* xyz = (const float*)d_in[0];
    const float* pts = (const float*)d_in[1];
    const float* w0  = (const float*)d_in[2];
    const float* b0  = (const float*)d_in[3];
    const float* g0  = (const float*)d_in[4];
    const float* be0 = (const float*)d_in[5];
    const float* w1  = (const float*)d_in[6];
    const float* b1  = (const float*)d_in[7];
    const float* g1  = (const float*)d_in[8];
    const float* be1 = (const float*)d_in[9];
    const float* w2  = (const float*)d_in[10];
    const float* b2  = (const float*)d_in[11];
    const float* g2  = (const float*)d_in[12];
    const float* be2 = (const float*)d_in[13];
    float* out = (float*)d_out;

    float *px0, *px1;
    cudaGetSymbolAddress((void**)&px0, g_x0);
    cudaGetSymbolAddress((void**)&px1, g_x1);

    cudaFuncSetAttribute(k_fps,    cudaFuncAttributeMaxDynamicSharedMemorySize, 98816);
    cudaFuncSetAttribute(k_ballq,  cudaFuncAttributeMaxDynamicSharedMemorySize, 131072);
    cudaFuncSetAttribute(k_layer0, cudaFuncAttributeMaxDynamicSharedMemorySize, 51456);
    cudaFuncSetAttribute(k_layer1, cudaFuncAttributeMaxDynamicSharedMemorySize, 49152);
    cudaFuncSetAttribute(k_layer2, cudaFuncAttributeMaxDynamicSharedMemorySize, 65536);

    k_fps  <<<BB, 1024, 98816>>>(xyz, out);
    k_ballq<<<BB*(SS/64), 256, 131072>>>(xyz, out);
    k_zero <<<1,128>>>();
    k_layer0<<<MM/128, 128, 51456>>>(xyz, pts, out, w0, b0);
    k_finalize<<<1,128>>>(g0, be0, 64);
    k_layer1<<<MM/128, 128, 49152>>>(px0, w1, b1, px1);
    k_finalize<<<1,128>>>(g1, be1, 64);
    k_layer2<<<MM/128, 256, 65536>>>(px1, w2, b2);
    k_finalize<<<1,128>>>(g2, be2, 128);
    k_pool <<<(BB*SS*128)/256, 256>>>(out);
}